// round 9
// baseline (speedup 1.0000x reference)
#include <cuda_runtime.h>
#include <cuda_fp16.h>
#include <cstdint>

// Problem constants
#define N_FEAT  65536
#define N_PROTO 512
#define DIMK    256

#define BLK_M   128                 // feature rows per CTA
#define BLK_N   64                  // prototypes per chunk
#define N_CHUNKS (N_PROTO / BLK_N)  // 8

// SMEM layout (bytes) — total 100 KB -> 2 CTAs / SM
#define SM_FSQ   0                          // 128 floats = 512 B
#define SM_PSQ   512                        // 512 floats = 2048 B
#define SM_A     4096                       // 8 mtiles * 16 ksteps * 512 B = 65536
#define SM_B     (SM_A + 65536)             // 8 ntiles * 16 ksteps * 256 B = 32768
#define SMEM_TOTAL (SM_B + 32768)           // 102400 B

// pack float2 -> fp16x2 (x -> low half)
__device__ __forceinline__ uint32_t pk(float2 f) {
    __half2 h = __floats2half2_rn(f.x, f.y);
    return *(uint32_t*)&h;
}

// m16n8k16 fp16 MMA, fp32 accumulate
__device__ __forceinline__ void mma_f16(float d[4], const uint32_t a[4], const uint32_t b[2]) {
    asm volatile(
        "mma.sync.aligned.m16n8k16.row.col.f32.f16.f16.f32 "
        "{%0,%1,%2,%3}, {%4,%5,%6,%7}, {%8,%9}, {%0,%1,%2,%3};"
        : "+f"(d[0]), "+f"(d[1]), "+f"(d[2]), "+f"(d[3])
        : "r"(a[0]), "r"(a[1]), "r"(a[2]), "r"(a[3]),
          "r"(b[0]), "r"(b[1]));
}

// ---------------------------------------------------------------------------
// Fragment SMEM layout (identity lane mapping, no swizzle, conflict-free):
//   A slab (mtile t, kstep s): 32 lanes x uint4 = 512 B  (m16n8k16 A frag)
//   B slab (ntile u, kstep s): 32 lanes x uint2 = 256 B  (col-major B frag)
// 256 threads, warp grid 4(M) x 2(N); per-warp tile T=2 mtiles x U=4 ntiles.
// Register double-buffer on k-steps hides LDS latency behind 8 MMAs.
// ---------------------------------------------------------------------------
__global__ void __launch_bounds__(256, 2) proto_dist_kernel(
    const float* __restrict__ feat,
    const float* __restrict__ proto,
    float* __restrict__ out1,    // [N, P]
    float* __restrict__ out2)    // [P, N]
{
    extern __shared__ char smem[];
    float* s_fsq = (float*)(smem + SM_FSQ);
    float* s_psq = (float*)(smem + SM_PSQ);

    const int tid  = threadIdx.x;
    const int lane = tid & 31;
    const int wid  = tid >> 5;   // 0..7
    const int g    = lane >> 2;
    const int tig  = lane & 3;
    const int m0   = blockIdx.x * BLK_M;

    // ---- Stage A tile (128 x 256) as fp16 fragments + exact fp32 feat norms ----
    {
        const int t = wid;                      // warp w stages mtile w (8 mtiles)
        const float* rA = feat + (size_t)(m0 + t * 16 + g) * DIMK;
        const float* rB = rA + 8 * DIMK;
        float sqA = 0.f, sqB = 0.f;
#pragma unroll
        for (int s = 0; s < 16; s++) {
            const int kA = s * 16 + 2 * tig;
            float2 f0 = *(const float2*)(rA + kA);
            float2 f1 = *(const float2*)(rB + kA);
            float2 f2 = *(const float2*)(rA + kA + 8);
            float2 f3 = *(const float2*)(rB + kA + 8);
            sqA += f0.x * f0.x + f0.y * f0.y + f2.x * f2.x + f2.y * f2.y;
            sqB += f1.x * f1.x + f1.y * f1.y + f3.x * f3.x + f3.y * f3.y;
            uint4 w;
            w.x = pk(f0); w.y = pk(f1); w.z = pk(f2); w.w = pk(f3);
            *(uint4*)(smem + SM_A + (size_t)((t * 16 + s) * 32 + lane) * 16) = w;
        }
        sqA += __shfl_xor_sync(0xffffffffu, sqA, 1);
        sqA += __shfl_xor_sync(0xffffffffu, sqA, 2);
        sqB += __shfl_xor_sync(0xffffffffu, sqB, 1);
        sqB += __shfl_xor_sync(0xffffffffu, sqB, 2);
        if (tig == 0) {
            s_fsq[t * 16 + g]     = sqA;
            s_fsq[t * 16 + g + 8] = sqB;
        }
    }

    // ---- All 512 prototype norms, exact fp32 (proto is L2-hot: 512 KB) ----
#pragma unroll
    for (int rr = 0; rr < 2; rr++) {
        const int row = rr * 256 + tid;
        const float4* r = (const float4*)(proto + (size_t)row * DIMK);
        float s0 = 0.f, s1 = 0.f;
#pragma unroll
        for (int j = 0; j < 64; j += 2) {
            float4 v0 = r[j], v1 = r[j + 1];
            s0 += v0.x * v0.x + v0.y * v0.y + v0.z * v0.z + v0.w * v0.w;
            s1 += v1.x * v1.x + v1.y * v1.y + v1.z * v1.z + v1.w * v1.w;
        }
        s_psq[row] = s0 + s1;
    }

    // ---- B staging: warp w stages ntile u=w (8 ntiles of 8 protos) ----
    auto stage_B = [&](int c) {
        const float* r = proto + (size_t)(c * BLK_N + wid * 8 + g) * DIMK;
#pragma unroll
        for (int s = 0; s < 16; s++) {
            const int kA = s * 16 + 2 * tig;
            float2 f0 = *(const float2*)(r + kA);
            float2 f1 = *(const float2*)(r + kA + 8);
            uint2 w;
            w.x = pk(f0); w.y = pk(f1);
            *(uint2*)(smem + SM_B + (size_t)((wid * 16 + s) * 32 + lane) * 8) = w;
        }
    };

    stage_B(0);

    // Warp grid: 4 (M) x 2 (N); per warp T=2 mtiles, U=4 ntiles
    const int mi = wid >> 1;
    const int nj = wid & 1;

    const char* baseA = smem + SM_A + (size_t)lane * 16;
    const char* baseB = smem + SM_B + (size_t)lane * 8;

    __syncthreads();   // A frags + B(chunk 0) + norms visible

    for (int c = 0; c < N_CHUNKS; c++) {
        const int p0 = c * BLK_N;

        float acc[2][4][4];
#pragma unroll
        for (int tp = 0; tp < 2; tp++)
#pragma unroll
            for (int up = 0; up < 4; up++)
#pragma unroll
                for (int e = 0; e < 4; e++) acc[tp][up][e] = 0.f;

        // register double-buffered mainloop over 16 k-steps
        uint4 a[2][2];
        uint2 b[2][4];
#pragma unroll
        for (int tp = 0; tp < 2; tp++)
            a[0][tp] = *(const uint4*)(baseA + (size_t)((mi * 2 + tp) * 16) * 512);
#pragma unroll
        for (int up = 0; up < 4; up++)
            b[0][up] = *(const uint2*)(baseB + (size_t)((nj * 4 + up) * 16) * 256);

#pragma unroll
        for (int s = 0; s < 16; s++) {
            const int cur = s & 1, nxt = cur ^ 1;
            if (s < 15) {
#pragma unroll
                for (int tp = 0; tp < 2; tp++)
                    a[nxt][tp] = *(const uint4*)(baseA +
                                 (size_t)((mi * 2 + tp) * 16 + s + 1) * 512);
#pragma unroll
                for (int up = 0; up < 4; up++)
                    b[nxt][up] = *(const uint2*)(baseB +
                                 (size_t)((nj * 4 + up) * 16 + s + 1) * 256);
            }
#pragma unroll
            for (int tp = 0; tp < 2; tp++)
#pragma unroll
                for (int up = 0; up < 4; up++)
                    mma_f16(acc[tp][up], (const uint32_t*)&a[cur][tp],
                            (const uint32_t*)&b[cur][up]);
        }

        __syncthreads();   // B(chunk c) fully consumed; buffer free to rewrite

        // Issue next chunk's staging LDGs first so their latency drains
        // underneath the store-heavy epilogue below.
        if (c + 1 < N_CHUNKS) stage_B(c + 1);

        // ---- Fused distance epilogue: direct stores for BOTH outputs ----
#pragma unroll
        for (int tp = 0; tp < 2; tp++) {
            const int ml0 = mi * 32 + tp * 16 + g;
            const int ml1 = ml0 + 8;
            const float fs0 = s_fsq[ml0];
            const float fs1 = s_fsq[ml1];
            float* o1a = out1 + (size_t)(m0 + ml0) * N_PROTO + p0;
            float* o1b = out1 + (size_t)(m0 + ml1) * N_PROTO + p0;
#pragma unroll
            for (int up = 0; up < 4; up++) {
                const int pl = nj * 32 + up * 8 + 2 * tig;
                const float2 ps = *(const float2*)(s_psq + p0 + pl);
                const float d0 = fs0 + ps.x - 2.0f * acc[tp][up][0];
                const float d1 = fs0 + ps.y - 2.0f * acc[tp][up][1];
                const float d2 = fs1 + ps.x - 2.0f * acc[tp][up][2];
                const float d3 = fs1 + ps.y - 2.0f * acc[tp][up][3];
                // out1 [N,P]: 4 tig-lanes x float2 = full 32B sector per row
                *(float2*)(o1a + pl) = make_float2(d0, d1);
                *(float2*)(o1b + pl) = make_float2(d2, d3);
                // out2 [P,N]: 8 g-lanes x 4B = full 32B sector per column
                float* o2 = out2 + (size_t)(p0 + pl) * N_FEAT + m0;
                o2[ml0]          = d0;
                o2[N_FEAT + ml0] = d1;
                o2[ml1]          = d2;
                o2[N_FEAT + ml1] = d3;
            }
        }

        if (c + 1 < N_CHUNKS) __syncthreads();   // B(chunk c+1) visible
    }
}

// ---------------------------------------------------------------------------
// Launch
// ---------------------------------------------------------------------------
extern "C" void kernel_launch(void* const* d_in, const int* in_sizes, int n_in,
                              void* d_out, int out_size)
{
    (void)in_sizes; (void)n_in; (void)out_size;
    const float* feat  = (const float*)d_in[0];
    const float* proto = (const float*)d_in[1];
    float* out1 = (float*)d_out;
    float* out2 = out1 + (size_t)N_FEAT * N_PROTO;

    cudaFuncSetAttribute(proto_dist_kernel,
                         cudaFuncAttributeMaxDynamicSharedMemorySize, SMEM_TOTAL);

    proto_dist_kernel<<<N_FEAT / BLK_M, 256, SMEM_TOTAL>>>(feat, proto, out1, out2);
}

// round 10
// speedup vs baseline: 1.3386x; 1.3386x over previous
#include <cuda_runtime.h>
#include <cuda_fp16.h>
#include <cstdint>

// Problem constants
#define N_FEAT  65536
#define N_PROTO 512
#define DIMK    256

#define BLK_M   256                 // feature rows per CTA
#define GRP_N   32                  // protos per group-chunk
#define N_CHUNKS 8                  // chunks per group (8 * 32 = 256 protos/group)

// SMEM layout (bytes)
#define SM_FSQ   0                          // 256 floats = 1024 B
#define SM_PSQ   1024                       // 512 floats = 2048 B
#define SM_A     4096                       // 16 mtiles * 16 ksteps * 512 B = 131072
#define SM_B     (SM_A + 131072)            // 2 grp * 2 buf * (4 ntiles*16 s*256 B=16384)
#define GRP_B_BYTES 32768                   // per group (double buffer)
#define BUF_BYTES   16384
#define SMEM_TOTAL (SM_B + 2 * GRP_B_BYTES) // 200704 B

// pack float2 -> fp16x2 (x -> low half)
__device__ __forceinline__ uint32_t pk(float2 f) {
    __half2 h = __floats2half2_rn(f.x, f.y);
    return *(uint32_t*)&h;
}

// m16n8k16 fp16 MMA, fp32 accumulate
__device__ __forceinline__ void mma_f16(float d[4], const uint32_t a[4], const uint32_t b[2]) {
    asm volatile(
        "mma.sync.aligned.m16n8k16.row.col.f32.f16.f16.f32 "
        "{%0,%1,%2,%3}, {%4,%5,%6,%7}, {%8,%9}, {%0,%1,%2,%3};"
        : "+f"(d[0]), "+f"(d[1]), "+f"(d[2]), "+f"(d[3])
        : "r"(a[0]), "r"(a[1]), "r"(a[2]), "r"(a[3]),
          "r"(b[0]), "r"(b[1]));
}

// named barrier over 256 threads (one warp group)
__device__ __forceinline__ void grp_bar(int id) {
    asm volatile("bar.sync %0, 256;" :: "r"(id) : "memory");
}

// ---------------------------------------------------------------------------
// Two independent 8-warp groups per CTA (grp = wid & 1). Each group owns a
// 256-proto half, a private double-buffered B region, and a private named
// barrier — so one group's LDS/MMA phase overlaps the other's STG burst.
// Fragment SMEM layout identical to R7 (identity lane map, conflict-free):
//   A slab (mtile t, kstep s): 32 lanes x uint4 = 512 B
//   B slab (ntile u, kstep s): 32 lanes x uint2 = 256 B
// Per-warp tile: T=2 mtiles x U=4 ntiles (the proven register shape).
// ---------------------------------------------------------------------------
__global__ void __launch_bounds__(512, 1) proto_dist_kernel(
    const float* __restrict__ feat,
    const float* __restrict__ proto,
    float* __restrict__ out1,    // [N, P]
    float* __restrict__ out2)    // [P, N]
{
    extern __shared__ char smem[];
    float* s_fsq = (float*)(smem + SM_FSQ);
    float* s_psq = (float*)(smem + SM_PSQ);

    const int tid  = threadIdx.x;
    const int lane = tid & 31;
    const int wid  = tid >> 5;     // 0..15
    const int g    = lane >> 2;
    const int tig  = lane & 3;
    const int m0   = blockIdx.x * BLK_M;

    const int grp  = wid & 1;      // warp group 0/1
    const int mi   = wid >> 1;     // 0..7 — M position (both groups cover all M)

    // ---- Stage A tile (256 x 256) as fp16 fragments + exact fp32 feat norms ----
    {
        const int t = wid;                       // warp w stages mtile w
        const float* rA = feat + (size_t)(m0 + t * 16 + g) * DIMK;
        const float* rB = rA + 8 * DIMK;
        float sqA = 0.f, sqB = 0.f;
#pragma unroll
        for (int s = 0; s < 16; s++) {
            const int kA = s * 16 + 2 * tig;
            float2 f0 = *(const float2*)(rA + kA);
            float2 f1 = *(const float2*)(rB + kA);
            float2 f2 = *(const float2*)(rA + kA + 8);
            float2 f3 = *(const float2*)(rB + kA + 8);
            sqA += f0.x * f0.x + f0.y * f0.y + f2.x * f2.x + f2.y * f2.y;
            sqB += f1.x * f1.x + f1.y * f1.y + f3.x * f3.x + f3.y * f3.y;
            uint4 w;
            w.x = pk(f0); w.y = pk(f1); w.z = pk(f2); w.w = pk(f3);
            *(uint4*)(smem + SM_A + (size_t)((t * 16 + s) * 32 + lane) * 16) = w;
        }
        sqA += __shfl_xor_sync(0xffffffffu, sqA, 1);
        sqA += __shfl_xor_sync(0xffffffffu, sqA, 2);
        sqB += __shfl_xor_sync(0xffffffffu, sqB, 1);
        sqB += __shfl_xor_sync(0xffffffffu, sqB, 2);
        if (tig == 0) {
            s_fsq[t * 16 + g]     = sqA;
            s_fsq[t * 16 + g + 8] = sqB;
        }
    }

    // ---- All 512 prototype norms, exact fp32 (proto is L2-hot: 512 KB) ----
    {
        const float4* r = (const float4*)(proto + (size_t)tid * DIMK);
        float s0 = 0.f, s1 = 0.f, s2 = 0.f, s3 = 0.f;
#pragma unroll
        for (int j = 0; j < 64; j += 4) {
            float4 v0 = r[j], v1 = r[j + 1], v2 = r[j + 2], v3 = r[j + 3];
            s0 += v0.x * v0.x + v0.y * v0.y + v0.z * v0.z + v0.w * v0.w;
            s1 += v1.x * v1.x + v1.y * v1.y + v1.z * v1.z + v1.w * v1.w;
            s2 += v2.x * v2.x + v2.y * v2.y + v2.z * v2.z + v2.w * v2.w;
            s3 += v3.x * v3.x + v3.y * v3.y + v3.z * v3.z + v3.w * v3.w;
        }
        s_psq[tid] = (s0 + s1) + (s2 + s3);
    }

    // ---- B staging: group grp, chunk c -> its buffer (c&1) ----
    // 8 warps/group: warp-in-group w2 = mi; u = mi>>1 (0..3), kstep half = mi&1.
    char* const grpB = smem + SM_B + grp * GRP_B_BYTES;
    const int pbase = grp * 256;           // group's proto half
    const int su = mi >> 1, sh = mi & 1;
    auto stage_B = [&](int c) {
        const float* r = proto + (size_t)(pbase + c * GRP_N + su * 8 + g) * DIMK;
        char* dst = grpB + (c & 1) * BUF_BYTES;
#pragma unroll
        for (int ss = 0; ss < 8; ss++) {
            const int s  = sh * 8 + ss;
            const int kA = s * 16 + 2 * tig;
            float2 f0 = *(const float2*)(r + kA);
            float2 f1 = *(const float2*)(r + kA + 8);
            uint2 w;
            w.x = pk(f0); w.y = pk(f1);
            *(uint2*)(dst + (size_t)((su * 16 + s) * 32 + lane) * 8) = w;
        }
    };

    stage_B(0);
    __syncthreads();   // A frags + norms + both groups' B(chunk 0) visible

    const char* baseA = smem + SM_A + (size_t)lane * 16;
    const int bar_id = 1 + grp;

    for (int c = 0; c < N_CHUNKS; c++) {
        const int p0 = pbase + c * GRP_N;
        const char* Bbuf = grpB + (c & 1) * BUF_BYTES + (size_t)lane * 8;

        float acc[2][4][4];
#pragma unroll
        for (int tp = 0; tp < 2; tp++)
#pragma unroll
            for (int up = 0; up < 4; up++)
#pragma unroll
                for (int e = 0; e < 4; e++) acc[tp][up][e] = 0.f;

#pragma unroll
        for (int s = 0; s < 16; s++) {
            uint4 a[2];
#pragma unroll
            for (int tp = 0; tp < 2; tp++)
                a[tp] = *(const uint4*)(baseA + (size_t)(((mi * 2 + tp) * 16 + s)) * 512);
            uint2 b[4];
#pragma unroll
            for (int up = 0; up < 4; up++)
                b[up] = *(const uint2*)(Bbuf + (size_t)((up * 16 + s) * 32) * 8);
#pragma unroll
            for (int tp = 0; tp < 2; tp++)
#pragma unroll
                for (int up = 0; up < 4; up++)
                    mma_f16(acc[tp][up], (const uint32_t*)&a[tp], (const uint32_t*)&b[up]);
        }

        // Stage next chunk into the other buffer. Safe: the group barrier at
        // the END of this iteration (below) separates this write from the
        // previous reader; the other buffer was last read in chunk c-1, and
        // every group warp passed the c-1 barrier already.
        if (c + 1 < N_CHUNKS) stage_B(c + 1);

        // ---- Fused distance epilogue: direct stores for BOTH outputs ----
#pragma unroll
        for (int tp = 0; tp < 2; tp++) {
            const int ml0 = mi * 32 + tp * 16 + g;
            const int ml1 = ml0 + 8;
            const float fs0 = s_fsq[ml0];
            const float fs1 = s_fsq[ml1];
            float* o1a = out1 + (size_t)(m0 + ml0) * N_PROTO + p0;
            float* o1b = out1 + (size_t)(m0 + ml1) * N_PROTO + p0;
#pragma unroll
            for (int up = 0; up < 4; up++) {
                const int pl = up * 8 + 2 * tig;
                const float2 ps = *(const float2*)(s_psq + p0 + pl);
                const float d0 = fs0 + ps.x - 2.0f * acc[tp][up][0];
                const float d1 = fs0 + ps.y - 2.0f * acc[tp][up][1];
                const float d2 = fs1 + ps.x - 2.0f * acc[tp][up][2];
                const float d3 = fs1 + ps.y - 2.0f * acc[tp][up][3];
                // out1 [N,P]: 4 tig-lanes x float2 = full 32B sector per row
                *(float2*)(o1a + pl) = make_float2(d0, d1);
                *(float2*)(o1b + pl) = make_float2(d2, d3);
                // out2 [P,N]: 8 g-lanes x 4B = full 32B sector per column
                float* o2 = out2 + (size_t)(p0 + pl) * N_FEAT + m0;
                o2[ml0]          = d0;
                o2[N_FEAT + ml0] = d1;
                o2[ml1]          = d2;
                o2[N_FEAT + ml1] = d3;
            }
        }

        // Group-private barrier: B(chunk c+1) visible to the 8 warps of this
        // group; all group warps done reading buffer (c&1).
        if (c + 1 < N_CHUNKS) grp_bar(bar_id);
    }
}

// ---------------------------------------------------------------------------
// Launch
// ---------------------------------------------------------------------------
extern "C" void kernel_launch(void* const* d_in, const int* in_sizes, int n_in,
                              void* d_out, int out_size)
{
    (void)in_sizes; (void)n_in; (void)out_size;
    const float* feat  = (const float*)d_in[0];
    const float* proto = (const float*)d_in[1];
    float* out1 = (float*)d_out;
    float* out2 = out1 + (size_t)N_FEAT * N_PROTO;

    cudaFuncSetAttribute(proto_dist_kernel,
                         cudaFuncAttributeMaxDynamicSharedMemorySize, SMEM_TOTAL);

    proto_dist_kernel<<<N_FEAT / BLK_M, 512, SMEM_TOTAL>>>(feat, proto, out1, out2);
}